// round 9
// baseline (speedup 1.0000x reference)
#include <cuda_runtime.h>
#include <cuda_bf16.h>
#include <cstdint>

#define NBINS   2200
#define NCHAN   12
#define NBATCH  32
#define PLANE   65536            // 256*256
#define SPLIT   3                // grid = 1152: single wave, ~90% occ
#define THREADS 256
#define N4PLANE (PLANE / 4)      // 16384 float4 per plane

// out = hist_counts (init before reductions; out is poisoned by harness)
__global__ void init_out_kernel(const float4* __restrict__ hist_in,
                                float4* __restrict__ out) {
    int i = blockIdx.x * blockDim.x + threadIdx.x;
    if (i < (NCHAN * NBINS) / 4) out[i] = hist_in[i];
}

// Returnless shared-memory reduction: no dest register, no scoreboard.
__device__ __forceinline__ void bin1(float f, unsigned int sh_base) {
    int idx = __float2int_rd(f + 1200.0f);
    // idx >= 0  <=>  f >= -1200 (floor is monotone); f <= 1000 kept exact
    // so values in (1000, 1001) are rejected (they'd floor into bin 2200).
    if (idx >= 0 && f <= 1000.0f) {
        unsigned int a = sh_base + 4u * (unsigned int)min(idx, NBINS - 1);
        asm volatile("red.shared.add.u32 [%0], %1;" :: "r"(a), "r"(1) : "memory");
    }
}

__device__ __forceinline__ void bin4(float4 v, unsigned int sh_base) {
    bin1(v.x, sh_base); bin1(v.y, sh_base);
    bin1(v.z, sh_base); bin1(v.w, sh_base);
}

__global__ __launch_bounds__(THREADS)
void hist_kernel(const float* __restrict__ x, float* __restrict__ out) {
    __shared__ int sh[NBINS];
    for (int i = threadIdx.x; i < NBINS; i += THREADS) sh[i] = 0;
    __syncthreads();

    const unsigned int sh_base =
        (unsigned int)__cvta_generic_to_shared(sh);

    const int block = blockIdx.x;          // 0 .. NBATCH*NCHAN*SPLIT-1
    const int plane = block / SPLIT;       // b * NCHAN + c  (B,C,H,W layout)
    const int part  = block % SPLIT;
    const int chan  = plane % NCHAN;

    const float4* __restrict__ p =
        reinterpret_cast<const float4*>(x) + (size_t)plane * N4PLANE;

    // Uneven thirds of the plane: [s, e) in float4 units.
    const int s = (part * N4PLANE) / SPLIT;
    const int e = ((part + 1) * N4PLANE) / SPLIT;

    int i = s + threadIdx.x;
    // Main loop: 2 front-batched cached loads per iteration.
    for (; i + THREADS < e; i += 2 * THREADS) {
        float4 a = p[i];
        float4 b = p[i + THREADS];
        bin4(a, sh_base);
        bin4(b, sh_base);
    }
    for (; i < e; i += THREADS) bin4(p[i], sh_base);
    __syncthreads();

    // Flush shared counts as exact returnless float reductions into out.
    float* __restrict__ g = out + chan * NBINS;
    for (int j = threadIdx.x; j < NBINS; j += THREADS) {
        int v = sh[j];
        if (v) {
            float fv = (float)v;
            asm volatile("red.global.add.f32 [%0], %1;"
                         :: "l"(&g[j]), "f"(fv) : "memory");
        }
    }
}

extern "C" void kernel_launch(void* const* d_in, const int* in_sizes, int n_in,
                              void* d_out, int out_size) {
    const float* x    = (const float*)d_in[0];       // [32,12,256,256] fp32
    const float* hist = (const float*)d_in[1];       // [12,2200] fp32
    float* out        = (float*)d_out;               // [12,2200] fp32

    const int n4 = (NCHAN * NBINS) / 4;              // 6600
    init_out_kernel<<<(n4 + 255) / 256, 256>>>((const float4*)hist, (float4*)out);
    hist_kernel<<<NBATCH * NCHAN * SPLIT, THREADS>>>(x, out);
}

// round 10
// speedup vs baseline: 1.0139x; 1.0139x over previous
#include <cuda_runtime.h>
#include <cuda_bf16.h>
#include <cstdint>

#define NBINS   2200
#define NCHAN   12
#define NBATCH  32
#define PLANE   65536            // 256*256
#define SPLIT   2                // grid = 768: single wave at 6 CTAs/SM (35KB smem)
#define THREADS 256
#define N4PLANE (PLANE / 4)      // 16384 float4 per plane
#define HALF4   (N4PLANE / SPLIT)
#define NREP    4                // interleaved histogram replicas (bank spread)
#define NCOPY   24               // blocks that copy hist_counts -> out up front
#define HIST4   ((NCHAN * NBINS) / 4)   // 6600 float4 of histogram state

// Self-resetting cross-block flags (persist across graph replays; last block
// resets them to 0, so every launch starts clean).
__device__ int g_done = 0;
__device__ int g_fin  = 0;

// Returnless shared reduction into replica (tid&3) of the interleaved layout.
__device__ __forceinline__ void bin1(float f, unsigned int rep_base) {
    int idx = __float2int_rd(f + 1200.0f);
    // idx >= 0  <=>  f >= -1200 (floor monotone). f <= 1000 exact: values in
    // (1000, 1001) must be rejected, f == 1000 maps to last bin via min.
    if (idx >= 0 && f <= 1000.0f) {
        unsigned int a = rep_base + 16u * (unsigned int)min(idx, NBINS - 1);
        asm volatile("red.shared.add.u32 [%0], %1;" :: "r"(a), "r"(1) : "memory");
    }
}

__device__ __forceinline__ void bin4(float4 v, unsigned int rep_base) {
    bin1(v.x, rep_base); bin1(v.y, rep_base);
    bin1(v.z, rep_base); bin1(v.w, rep_base);
}

__global__ __launch_bounds__(THREADS)
void hist_kernel(const float* __restrict__ x,
                 const float4* __restrict__ hist_in,
                 float* __restrict__ out) {
    __shared__ int sh[NREP * NBINS];          // 35.2 KB, interleaved: [idx*4 + r]

    // ---- Prologue A: first NCOPY blocks publish out = hist_counts ----
    if (blockIdx.x < NCOPY) {
        float4* __restrict__ o4 = reinterpret_cast<float4*>(out);
        const int per = HIST4 / NCOPY;        // 275
        const int base = blockIdx.x * per;
        for (int i = threadIdx.x; i < per; i += THREADS)
            o4[base + i] = hist_in[base + i];
        __threadfence();
        if (threadIdx.x == 0) atomicAdd(&g_done, 1);
    }

    // ---- Prologue B: zero replicas ----
    {
        int4* s4 = reinterpret_cast<int4*>(sh);
        const int4 z = make_int4(0, 0, 0, 0);
        for (int i = threadIdx.x; i < NBINS; i += THREADS) s4[i] = z;
    }
    __syncthreads();

    const unsigned int sh_base = (unsigned int)__cvta_generic_to_shared(sh);
    const unsigned int rep_base = sh_base + 4u * (threadIdx.x & (NREP - 1));

    const int plane = blockIdx.x >> 1;        // b * NCHAN + c  (B,C,H,W layout)
    const int part  = blockIdx.x & 1;
    const int chan  = plane % NCHAN;

    const float4* __restrict__ p = reinterpret_cast<const float4*>(x)
        + (size_t)plane * N4PLANE + (size_t)part * HALF4;

    // 8192 float4 / 256 threads = 32 per thread; 2 front-batched loads/iter.
    #pragma unroll
    for (int i = threadIdx.x; i < HALF4; i += 2 * THREADS) {
        float4 a = p[i];
        float4 b = p[i + THREADS];
        bin4(a, rep_base);
        bin4(b, rep_base);
    }
    __syncthreads();

    // ---- Wait until out is initialized (long satisfied by now) ----
    if (threadIdx.x == 0) {
        while (atomicAdd(&g_done, 0) < NCOPY) { }
    }
    __syncthreads();
    __threadfence();

    // ---- Merge replicas + flush as exact returnless float reductions ----
    float* __restrict__ g = out + chan * NBINS;
    const int4* s4 = reinterpret_cast<const int4*>(sh);
    for (int j = threadIdx.x; j < NBINS; j += THREADS) {
        int4 v = s4[j];                        // conflict-free LDS.128
        int t = v.x + v.y + v.z + v.w;
        if (t) {
            float fv = (float)t;
            asm volatile("red.global.add.f32 [%0], %1;"
                         :: "l"(&g[j]), "f"(fv) : "memory");
        }
    }

    // ---- Self-clean flags for the next graph replay ----
    __syncthreads();
    if (threadIdx.x == 0) {
        if (atomicAdd(&g_fin, 1) == (int)gridDim.x - 1) {
            atomicExch(&g_fin, 0);
            atomicExch(&g_done, 0);
        }
    }
}

extern "C" void kernel_launch(void* const* d_in, const int* in_sizes, int n_in,
                              void* d_out, int out_size) {
    const float* x    = (const float*)d_in[0];       // [32,12,256,256] fp32
    const float* hist = (const float*)d_in[1];       // [12,2200] fp32
    float* out        = (float*)d_out;               // [12,2200] fp32

    hist_kernel<<<NBATCH * NCHAN * SPLIT, THREADS>>>(
        x, (const float4*)hist, out);
}